// round 1
// baseline (speedup 1.0000x reference)
#include <cuda_runtime.h>
#include <cuda_bf16.h>

// Rows = 4194304, features = 16 fp32 per row, output = rows x 3 fp32 one-hot.
// selected = (f11 > 0.5) ? 0 : ((f4+f5 > f6+f7) ? 1 : 2)

#define ROWS_PER_THREAD 4

__global__ __launch_bounds__(256)
void gating_kernel(const float4* __restrict__ in,   // viewed as float4: 4 per row
                   float4* __restrict__ out,        // 3 float4 per 4 rows
                   int n_rows)
{
    int t = blockIdx.x * blockDim.x + threadIdx.x;     // thread id
    int row0 = t * ROWS_PER_THREAD;
    if (row0 >= n_rows) return;

    // Per row r: float4 #1 = cols 4..7, float4 #2 = cols 8..11 (.w = col 11)
    // Batch all loads up front for MLP.
    float4 c47[ROWS_PER_THREAD];
    float  c11[ROWS_PER_THREAD];
#pragma unroll
    for (int i = 0; i < ROWS_PER_THREAD; i++) {
        int r = row0 + i;
        c47[i] = in[r * 4 + 1];
        c11[i] = in[r * 4 + 2].w;   // compiler emits scalar LDG.32 of the .w lane
    }

    float o[ROWS_PER_THREAD * 3];
#pragma unroll
    for (int i = 0; i < ROWS_PER_THREAD; i++) {
        float cyc = c47[i].x + c47[i].y;   // f4 + f5
        float hf  = c47[i].z + c47[i].w;   // f6 + f7
        bool e0 = c11[i] > 0.5f;
        bool e1 = !e0 && (cyc > hf);
        bool e2 = !e0 && !e1;
        o[i * 3 + 0] = e0 ? 1.0f : 0.0f;
        o[i * 3 + 1] = e1 ? 1.0f : 0.0f;
        o[i * 3 + 2] = e2 ? 1.0f : 0.0f;
    }

    // 4 rows * 3 floats = 12 floats = 3 float4, base aligned (t * 48 bytes)
    float4* dst = out + t * 3;
    dst[0] = make_float4(o[0], o[1], o[2],  o[3]);
    dst[1] = make_float4(o[4], o[5], o[6],  o[7]);
    dst[2] = make_float4(o[8], o[9], o[10], o[11]);
}

extern "C" void kernel_launch(void* const* d_in, const int* in_sizes, int n_in,
                              void* d_out, int out_size)
{
    const float* features = (const float*)d_in[0];
    float* out = (float*)d_out;
    int n_rows = in_sizes[0] / 16;          // 4194304

    int n_threads = n_rows / ROWS_PER_THREAD;      // exact: 1048576
    int block = 256;
    int grid = (n_threads + block - 1) / block;    // 4096
    gating_kernel<<<grid, block>>>((const float4*)features, (float4*)out, n_rows);
}